// round 11
// baseline (speedup 1.0000x reference)
#include <cuda_runtime.h>
#include <stdint.h>

// B=128, N=256, T=1024, C=10
#define T_LEN   1024
#define N_NEUR  256
#define C_GAP   10
#define WPB     8
#define THREADS (WPB * 32)
#define NEGINF  (-3.402823466e38f)
#define FULL    0xffffffffu
#define MAXCL   96
#define TILE_ROWS  8
#define TILE_BYTES (TILE_ROWS * T_LEN * 4)     // 32 KB
#define NBUF    2
#define SMEM_DYN (NBUF * TILE_BYTES)           // 64 KB
#define GRIDN   444                            // 3 blocks/SM * 148 SMs
#define NTILES  (128 * 256 / TILE_ROWS)        // 4096

__device__ float    g_loss;     // zero-init; reset by last block each launch
__device__ unsigned g_tick;
__device__ unsigned g_tile;     // work-stealing tile counter; reset each launch

extern __shared__ float dbuf[];

__device__ __forceinline__ void mbar_wait(unsigned bar, int phase) {
    asm volatile(
        "{\n\t.reg .pred P;\n\t"
        "W%=:\n\t"
        "mbarrier.try_wait.parity.acquire.cta.shared::cta.b64 P, [%0], %1, 0x989680;\n\t"
        "@P bra.uni D%=;\n\t"
        "bra.uni W%=;\n\t"
        "D%=:\n\t}"
        :: "r"(bar), "r"(phase) : "memory");
}

__device__ __forceinline__ void issue_tile(unsigned dst, const float* src, unsigned bar) {
    asm volatile("mbarrier.arrive.expect_tx.shared.b64 _, [%0], %1;"
                 :: "r"(bar), "r"((unsigned)TILE_BYTES) : "memory");
    asm volatile("cp.async.bulk.shared::cluster.global.mbarrier::complete_tx::bytes "
                 "[%0], [%1], %2, [%3];"
                 :: "r"(dst), "l"(src), "r"((unsigned)TILE_BYTES), "r"(bar) : "memory");
}

// Process one row resident in smem at sbase. Result warp-uniform.
__device__ __forceinline__ float process_row(unsigned sbase, int row, int l,
                                             unsigned* shp, unsigned* shcl,
                                             const int*   __restrict__ labels,
                                             float*       __restrict__ out)
{
    const bool lane0 = (l == 0);

    // Sync-free nibble packing: bit (4k+j) <-> time 128k+4l+j
    float maxall = NEGINF;
    unsigned pack = 0;
    #pragma unroll
    for (int k = 0; k < 8; ++k) {
        float4 v;
        unsigned a = sbase + (unsigned)((k * 32 + l) * 16);
        asm volatile("ld.shared.v4.f32 {%0,%1,%2,%3}, [%4];"
                     : "=f"(v.x), "=f"(v.y), "=f"(v.z), "=f"(v.w) : "r"(a));
        maxall = fmaxf(maxall, fmaxf(fmaxf(v.x, v.y), fmaxf(v.z, v.w)));
        unsigned nib = (v.x >= 0.0f ? 1u : 0u)
                     | (v.y >= 0.0f ? 2u : 0u)
                     | (v.z >= 0.0f ? 4u : 0u)
                     | (v.w >= 0.0f ? 8u : 0u);
        pack |= nib << (4 * k);
    }
    shp[l] = pack;
    __syncwarp();

    // Window mask for window l (times [32l, 32l+32))
    unsigned m = 0;
    {
        const unsigned ksh = 4 * (l >> 2);
        const unsigned* src = &shp[8 * (l & 3)];
        #pragma unroll
        for (int i = 0; i < 8; ++i)
            m |= ((src[i] >> ksh) & 0xFu) << (4 * i);
    }

    // Cluster-start mask: spike with no spike in previous C steps
    unsigned prev = __shfl_up_sync(FULL, m, 1);
    if (lane0) prev = 0;
    unsigned long long A  = ((unsigned long long)m << 32) | prev;
    unsigned long long t1 = (A << 1) | (A << 2);          // shifts {1,2}
    unsigned long long t2 = t1 | (t1 << 2);               // {1..4}
    unsigned long long t3 = t2 | (t2 << 4);               // {1..8}
    unsigned long long sp = t3 | (t1 << 8);               // {1..10}
    unsigned starts = m & ~(unsigned)(sp >> 32);

    const int sc = __popc(starts);
    const int nc = __reduce_add_sync(FULL, sc);

    const int b_     = row >> 8;
    const int nn     = row & (N_NEUR - 1);
    const int target = (__ldg(labels + b_) == nn) ? 1 : 0;

    float contrib = 0.0f;
    if (nc > target) {                       // warp-uniform
        if (nc == 1) {
            #pragma unroll
            for (int d = 16; d > 0; d >>= 1)
                maxall = fmaxf(maxall, __shfl_xor_sync(FULL, maxall, d));
            contrib = maxall;                // single cluster: span max == row max
        } else {
            const int pc = __popc(m);
            int ipc = pc, isc = sc;
            #pragma unroll
            for (int d = 1; d < 32; d <<= 1) {
                int vp = __shfl_up_sync(FULL, ipc, d);
                int vs = __shfl_up_sync(FULL, isc, d);
                if (l >= d) { ipc += vp; isc += vs; }
            }
            const int excl  = ipc - pc;
            int c           = isc - sc;
            const int S_tot = __shfl_sync(FULL, ipc, 31);

            unsigned sm_ = starts;
            const int tb = l * 32;
            while (sm_) {
                int bit = __ffs(sm_) - 1;
                sm_ &= sm_ - 1;
                int sb = excl + __popc(m & ((1u << bit) - 1u));
                shcl[c] = ((unsigned)sb << 16) | (unsigned)(tb + bit);
                ++c;
            }
            if (lane0) shcl[nc] = ((unsigned)S_tot << 16) | (unsigned)T_LEN;
            __syncwarp();

            int best = 0x7fffffff;
            for (int c0 = l; c0 < nc; c0 += 32) {
                unsigned a  = shcl[c0];
                unsigned bn = shcl[c0 + 1];
                int size = (int)(bn >> 16) - (int)(a >> 16);
                best = min(best, (size << 7) | c0);
            }
            best = __reduce_min_sync(FULL, (unsigned)best);
            const int cstar = best & 127;
            const unsigned a  = shcl[cstar];
            const unsigned bn = shcl[cstar + 1];
            const int cb  = (int)(a  & 0xffffu);
            const int ceN = (int)(bn & 0xffffu);
            const unsigned width = (unsigned)(ceN - cb);

            // span max from the smem tile (still resident)
            float smax = NEGINF;
            const int ks = cb >> 7, ke = (ceN - 1) >> 7;
            for (int k = ks; k <= ke; ++k) {
                float4 v;
                unsigned aa = sbase + (unsigned)((k * 32 + l) * 16);
                asm volatile("ld.shared.v4.f32 {%0,%1,%2,%3}, [%4];"
                             : "=f"(v.x), "=f"(v.y), "=f"(v.z), "=f"(v.w) : "r"(aa));
                int t0 = k * 128 + 4 * l;
                if ((unsigned)(t0     - cb) < width) smax = fmaxf(smax, v.x);
                if ((unsigned)(t0 + 1 - cb) < width) smax = fmaxf(smax, v.y);
                if ((unsigned)(t0 + 2 - cb) < width) smax = fmaxf(smax, v.z);
                if ((unsigned)(t0 + 3 - cb) < width) smax = fmaxf(smax, v.w);
            }
            #pragma unroll
            for (int d = 16; d > 0; d >>= 1)
                smax = fmaxf(smax, __shfl_xor_sync(FULL, smax, d));
            contrib = smax;
        }
    } else if (nc == 0 && target) {
        #pragma unroll
        for (int d = 16; d > 0; d >>= 1)
            maxall = fmaxf(maxall, __shfl_xor_sync(FULL, maxall, d));
        contrib = -maxall;
    }

    if (lane0) out[1 + row] = (float)nc;     // spike_output
    return contrib;
}

__global__ __launch_bounds__(THREADS)
void stca_main(const float* __restrict__ vmem,
               const int*   __restrict__ labels,
               float*       __restrict__ out)
{
    __shared__ unsigned sh_p[WPB][32];
    __shared__ unsigned sh_cl[WPB][MAXCL];
    __shared__ float    warp_contrib[WPB];
    __shared__ int      sh_tile[NBUF];
    __shared__ alignas(8) unsigned long long mbar[NBUF];

    const int tid = threadIdx.x;
    const int w   = tid >> 5;
    const int l   = tid & 31;

    const unsigned smem0 = (unsigned)__cvta_generic_to_shared(dbuf);
    unsigned baraddr[NBUF];
    #pragma unroll
    for (int i = 0; i < NBUF; ++i)
        baraddr[i] = (unsigned)__cvta_generic_to_shared(&mbar[i]);

    if (tid == 0) {
        asm volatile("mbarrier.init.shared.b64 [%0], 1;" :: "r"(baraddr[0]) : "memory");
        asm volatile("mbarrier.init.shared.b64 [%0], 1;" :: "r"(baraddr[1]) : "memory");
    }
    __syncthreads();
    asm volatile("fence.proxy.async.shared::cta;" ::: "memory");

    // Prologue: grab and issue first two tiles (work stealing).
    if (tid == 0) {
        int t0 = (int)atomicAdd(&g_tile, 1u);
        int t1 = (int)atomicAdd(&g_tile, 1u);
        sh_tile[0] = t0;
        sh_tile[1] = t1;
        if (t0 < NTILES)
            issue_tile(smem0, vmem + (size_t)t0 * TILE_ROWS * T_LEN, baraddr[0]);
        if (t1 < NTILES)
            issue_tile(smem0 + TILE_BYTES,
                       vmem + (size_t)t1 * TILE_ROWS * T_LEN, baraddr[1]);
    }
    __syncthreads();

    int ph0 = 0, ph1 = 0;
    float lsum = 0.0f;

    for (int i = 0; ; ++i) {
        const int b    = i & 1;
        const int tile = sh_tile[b];        // fresh: last write separated by a barrier
        if (tile >= NTILES) break;          // grabs monotonic per buffer order -> safe

        const unsigned sb = smem0 + (unsigned)b * TILE_BYTES;
        if (b == 0) { mbar_wait(baraddr[0], ph0); ph0 ^= 1; }
        else        { mbar_wait(baraddr[1], ph1); ph1 ^= 1; }

        lsum += process_row(sb + (unsigned)(w * T_LEN * 4),
                            tile * TILE_ROWS + w, l,
                            sh_p[w], sh_cl[w], labels, out);
        __syncthreads();                    // all warps done reading buffer b

        if (tid == 0) {                     // steal next tile, refill buffer b
            int nt = (int)atomicAdd(&g_tile, 1u);
            sh_tile[b] = nt;
            if (nt < NTILES)
                issue_tile(sb, vmem + (size_t)nt * TILE_ROWS * T_LEN, baraddr[b]);
        }
        // sh_tile[b] next read at i+2; the syncthreads inside iteration i+1
        // (or loop exit path below) orders the write before that read.
    }
    __syncthreads();

    if (l == 0) warp_contrib[w] = lsum;
    __syncthreads();

    // grid reduction: device accumulator + ticket (graph-replay safe)
    if (tid == 0) {
        float s = 0.0f;
        #pragma unroll
        for (int i = 0; i < WPB; ++i) s += warp_contrib[i];
        atomicAdd(&g_loss, s);
        __threadfence();
        unsigned t = atomicAdd(&g_tick, 1u);
        if (t == gridDim.x - 1) {            // last block: publish + reset for replay
            __threadfence();
            out[0] = g_loss;
            g_loss = 0.0f;
            g_tick = 0u;
            g_tile = 0u;
        }
    }
}

extern "C" void kernel_launch(void* const* d_in, const int* in_sizes, int n_in,
                              void* d_out, int out_size) {
    const float* vmem   = (const float*)d_in[0];   // [128,256,1024] f32
    // d_in[1] = vlastmem — unused by the reference forward; deliberately not read
    const int*   labels = (const int*)d_in[2];     // [128] i32
    float*       out    = (float*)d_out;           // [1 + 128*256] f32

    static bool attr_set = false;                  // host-side only
    if (!attr_set) {
        cudaFuncSetAttribute(stca_main, cudaFuncAttributeMaxDynamicSharedMemorySize, SMEM_DYN);
        attr_set = true;
    }
    stca_main<<<GRIDN, THREADS, SMEM_DYN>>>(vmem, labels, out);
}